// round 1
// baseline (speedup 1.0000x reference)
#include <cuda_runtime.h>
#include <cuda_bf16.h>
#include <cstdint>
#include <cstddef>

// ---------------------------------------------------------------------------
// Problem constants
// ---------------------------------------------------------------------------
static constexpr int BATCH   = 2;
static constexpr int SEQ     = 2048;
static constexpr int HID     = 4096;
static constexpr int NHEADS  = 32;
static constexpr int HDIM    = 128;
static constexpr int QRANK   = 1536;
static constexpr int KVRANK  = 512;
static constexpr int TOKENS  = BATCH * SEQ;            // 4096
static constexpr int MODEL   = NHEADS * HDIM;          // 4096
static constexpr float SM_SCALE = 0.08838834764831845f; // 1/sqrt(128)

// ---------------------------------------------------------------------------
// Scratch (static device allocations; no cudaMalloc anywhere)
// ---------------------------------------------------------------------------
__device__ float g_qc[(size_t)TOKENS * QRANK];    // 25 MB
__device__ float g_q [(size_t)TOKENS * MODEL];    // 67 MB
__device__ float g_k [(size_t)TOKENS * MODEL];    // 67 MB
__device__ float g_v [(size_t)TOKENS * MODEL];    // 67 MB
__device__ float g_ao[(size_t)TOKENS * MODEL];    // 67 MB

// ---------------------------------------------------------------------------
// Generic fp32 SGEMM:  C[M,N] = A[M,K] * B[K,N]   (row-major, all dims % tile == 0)
// 128x128 tile, BK=8, 256 threads, 8x8 per thread.
// ---------------------------------------------------------------------------
static constexpr int GBM = 128, GBN = 128, GBK = 8;

__global__ __launch_bounds__(256) void sgemm_kernel(
    const float* __restrict__ A, const float* __restrict__ B,
    float* __restrict__ C, int M, int N, int K)
{
    __shared__ float As[GBK][GBM + 4];
    __shared__ float Bs[GBK][GBN + 4];

    const int tid = threadIdx.x;
    const int m0 = blockIdx.y * GBM;
    const int n0 = blockIdx.x * GBN;
    const int tx = tid & 15;       // 0..15 -> N
    const int ty = tid >> 4;       // 0..15 -> M

    // global-load mapping
    const int arow = tid >> 1;            // 0..127
    const int acol = (tid & 1) * 4;       // 0 or 4
    const int brow = tid >> 5;            // 0..7
    const int bcol = (tid & 31) * 4;      // 0..124

    float acc[8][8];
#pragma unroll
    for (int i = 0; i < 8; i++)
#pragma unroll
        for (int j = 0; j < 8; j++) acc[i][j] = 0.f;

    const float* Aptr = A + (size_t)(m0 + arow) * K + acol;
    const float* Bptr = B + (size_t)brow * N + n0 + bcol;

    for (int k0 = 0; k0 < K; k0 += GBK) {
        float4 a4 = *(const float4*)(Aptr + k0);
        float4 b4 = *(const float4*)(Bptr + (size_t)k0 * N);
        __syncthreads();   // previous iteration's smem reads complete
        As[acol + 0][arow] = a4.x;
        As[acol + 1][arow] = a4.y;
        As[acol + 2][arow] = a4.z;
        As[acol + 3][arow] = a4.w;
        *(float4*)&Bs[brow][bcol] = b4;
        __syncthreads();

#pragma unroll
        for (int k = 0; k < GBK; k++) {
            float4 a0 = *(const float4*)&As[k][ty * 4];
            float4 a1 = *(const float4*)&As[k][64 + ty * 4];
            float4 b0 = *(const float4*)&Bs[k][tx * 4];
            float4 b1 = *(const float4*)&Bs[k][64 + tx * 4];
            float av[8] = {a0.x, a0.y, a0.z, a0.w, a1.x, a1.y, a1.z, a1.w};
            float bv[8] = {b0.x, b0.y, b0.z, b0.w, b1.x, b1.y, b1.z, b1.w};
#pragma unroll
            for (int i = 0; i < 8; i++)
#pragma unroll
                for (int j = 0; j < 8; j++)
                    acc[i][j] = fmaf(av[i], bv[j], acc[i][j]);
        }
    }

#pragma unroll
    for (int i = 0; i < 8; i++) {
        int m = m0 + ((i < 4) ? (ty * 4 + i) : (64 + ty * 4 + (i - 4)));
        float4 c0 = make_float4(acc[i][0], acc[i][1], acc[i][2], acc[i][3]);
        float4 c1 = make_float4(acc[i][4], acc[i][5], acc[i][6], acc[i][7]);
        *(float4*)&C[(size_t)m * N + n0 + tx * 4]      = c0;
        *(float4*)&C[(size_t)m * N + n0 + 64 + tx * 4] = c1;
    }
}

// ---------------------------------------------------------------------------
// Flash attention (causal), fp32. Tile 64 queries x 64 keys, HDIM=128.
// Grid: (SEQ/64, NHEADS, BATCH). Block: 256 threads.
// Q/K/V/O layout: [token, head*128 + d] with token = b*SEQ + s.
// ---------------------------------------------------------------------------
static constexpr int FTM = 64;           // query tile
static constexpr int FTN = 64;           // key tile
static constexpr int QS_LD = HDIM + 4;   // 132
static constexpr int PS_LD = FTN + 4;    // 68
static constexpr int FLASH_SMEM_FLOATS =
    3 * FTM * QS_LD + FTM * PS_LD + 3 * FTM;   // Qs,Ks,Vs,Ps,rmax,rsum,corr
static constexpr int FLASH_SMEM_BYTES = FLASH_SMEM_FLOATS * 4;  // 119,552 B

extern __shared__ float fsh[];

__global__ __launch_bounds__(256) void flash_kernel(
    const float* __restrict__ Q, const float* __restrict__ K,
    const float* __restrict__ V, float* __restrict__ O)
{
    float* Qs   = fsh;
    float* Ks   = Qs + FTM * QS_LD;
    float* Vs   = Ks + FTM * QS_LD;
    float* Ps   = Vs + FTM * QS_LD;
    float* rmax = Ps + FTM * PS_LD;
    float* rsum = rmax + FTM;
    float* corr = rsum + FTM;

    const int tid   = threadIdx.x;
    const int mtile = blockIdx.x;
    const int head  = blockIdx.y;
    const int b     = blockIdx.z;
    const int m0    = mtile * FTM;
    const size_t base = ((size_t)b * SEQ) * MODEL + (size_t)head * HDIM;

    // load Q tile (64 x 128) with float4
    for (int it = tid; it < FTM * (HDIM / 4); it += 256) {
        int r  = it >> 5;
        int c4 = (it & 31) << 2;
        *(float4*)&Qs[r * QS_LD + c4] =
            *(const float4*)&Q[base + (size_t)(m0 + r) * MODEL + c4];
    }
    if (tid < FTM) { rmax[tid] = -1e30f; rsum[tid] = 0.f; }

    const int sm = tid >> 4;   // 0..15 -> 4 rows each
    const int sn = tid & 15;   // 0..15 -> 4 score cols / 8 out dims

    float o[4][8];
#pragma unroll
    for (int i = 0; i < 4; i++)
#pragma unroll
        for (int j = 0; j < 8; j++) o[i][j] = 0.f;

    const int ntiles = mtile + 1;   // causal: keys up to and including diagonal tile
    for (int t = 0; t < ntiles; t++) {
        const int n0 = t * FTN;
        __syncthreads();   // prior PV reads of Ks/Vs/Ps complete
        for (int it = tid; it < FTN * (HDIM / 4); it += 256) {
            int r  = it >> 5;
            int c4 = (it & 31) << 2;
            size_t g = base + (size_t)(n0 + r) * MODEL + c4;
            *(float4*)&Ks[r * QS_LD + c4] = *(const float4*)&K[g];
            *(float4*)&Vs[r * QS_LD + c4] = *(const float4*)&V[g];
        }
        __syncthreads();

        // ---- scores: s[4][4] = Q(4 rows) . K(4 cols) ----
        float s[4][4];
#pragma unroll
        for (int i = 0; i < 4; i++)
#pragma unroll
            for (int j = 0; j < 4; j++) s[i][j] = 0.f;

#pragma unroll 4
        for (int d4 = 0; d4 < HDIM / 4; d4++) {
            float4 qa[4], kb[4];
#pragma unroll
            for (int i = 0; i < 4; i++)
                qa[i] = *(const float4*)&Qs[(sm * 4 + i) * QS_LD + d4 * 4];
#pragma unroll
            for (int j = 0; j < 4; j++)
                kb[j] = *(const float4*)&Ks[(sn * 4 + j) * QS_LD + d4 * 4];
#pragma unroll
            for (int i = 0; i < 4; i++)
#pragma unroll
                for (int j = 0; j < 4; j++) {
                    s[i][j] = fmaf(qa[i].x, kb[j].x, s[i][j]);
                    s[i][j] = fmaf(qa[i].y, kb[j].y, s[i][j]);
                    s[i][j] = fmaf(qa[i].z, kb[j].z, s[i][j]);
                    s[i][j] = fmaf(qa[i].w, kb[j].w, s[i][j]);
                }
        }

        // mask + scale
#pragma unroll
        for (int i = 0; i < 4; i++) {
            int mq = m0 + sm * 4 + i;
#pragma unroll
            for (int j = 0; j < 4; j++) {
                int kn = n0 + sn * 4 + j;
                s[i][j] = (kn <= mq) ? s[i][j] * SM_SCALE : -1e30f;
            }
        }

        // ---- online softmax per row (16 lanes per row group, same warp) ----
#pragma unroll
        for (int i = 0; i < 4; i++) {
            const int row = sm * 4 + i;
            float tmax = fmaxf(fmaxf(s[i][0], s[i][1]), fmaxf(s[i][2], s[i][3]));
#pragma unroll
            for (int off = 1; off < 16; off <<= 1)
                tmax = fmaxf(tmax, __shfl_xor_sync(0xffffffffu, tmax, off));
            float oldmax = rmax[row];
            float nmax = fmaxf(oldmax, tmax);
            float p0 = __expf(s[i][0] - nmax);
            float p1 = __expf(s[i][1] - nmax);
            float p2 = __expf(s[i][2] - nmax);
            float p3 = __expf(s[i][3] - nmax);
            float tsum = p0 + p1 + p2 + p3;
#pragma unroll
            for (int off = 1; off < 16; off <<= 1)
                tsum += __shfl_xor_sync(0xffffffffu, tsum, off);
            float c = __expf(oldmax - nmax);
            if (sn == 0) {
                rmax[row] = nmax;
                rsum[row] = rsum[row] * c + tsum;
                corr[row] = c;
            }
            *(float4*)&Ps[row * PS_LD + sn * 4] = make_float4(p0, p1, p2, p3);
        }
        __syncthreads();

        // ---- PV: rows sm*4.., out dims sn*8.. ----
#pragma unroll
        for (int i = 0; i < 4; i++) {
            float c = corr[sm * 4 + i];
#pragma unroll
            for (int j = 0; j < 8; j++) o[i][j] *= c;
        }
#pragma unroll 4
        for (int kk = 0; kk < FTN; kk++) {
            float4 v0 = *(const float4*)&Vs[kk * QS_LD + sn * 8];
            float4 v1 = *(const float4*)&Vs[kk * QS_LD + sn * 8 + 4];
#pragma unroll
            for (int i = 0; i < 4; i++) {
                float p = Ps[(sm * 4 + i) * PS_LD + kk];
                o[i][0] = fmaf(p, v0.x, o[i][0]);
                o[i][1] = fmaf(p, v0.y, o[i][1]);
                o[i][2] = fmaf(p, v0.z, o[i][2]);
                o[i][3] = fmaf(p, v0.w, o[i][3]);
                o[i][4] = fmaf(p, v1.x, o[i][4]);
                o[i][5] = fmaf(p, v1.y, o[i][5]);
                o[i][6] = fmaf(p, v1.z, o[i][6]);
                o[i][7] = fmaf(p, v1.w, o[i][7]);
            }
        }
    }
    __syncthreads();   // ensure rsum final

    // ---- epilogue: O = o / rsum ----
#pragma unroll
    for (int i = 0; i < 4; i++) {
        int row = sm * 4 + i;
        float inv = 1.f / rsum[row];
        float4 w0 = make_float4(o[i][0] * inv, o[i][1] * inv, o[i][2] * inv, o[i][3] * inv);
        float4 w1 = make_float4(o[i][4] * inv, o[i][5] * inv, o[i][6] * inv, o[i][7] * inv);
        size_t g = base + (size_t)(m0 + row) * MODEL + sn * 8;
        *(float4*)&O[g]     = w0;
        *(float4*)&O[g + 4] = w1;
    }
}

// ---------------------------------------------------------------------------
// Launch
// ---------------------------------------------------------------------------
static inline void run_sgemm(const float* A, const float* B, float* C,
                             int M, int N, int K, cudaStream_t stream)
{
    dim3 grid(N / GBN, M / GBM);
    sgemm_kernel<<<grid, 256, 0, stream>>>(A, B, C, M, N, K);
}

extern "C" void kernel_launch(void* const* d_in, const int* in_sizes, int n_in,
                              void* d_out, int out_size)
{
    (void)in_sizes; (void)n_in; (void)out_size;
    const float* X     = (const float*)d_in[0];  // [2,2048,4096]
    const float* w_qa  = (const float*)d_in[1];  // [4096,1536]
    const float* w_qb  = (const float*)d_in[2];  // [1536,4096]
    const float* w_kva = (const float*)d_in[3];  // [4096,512]
    const float* w_kb  = (const float*)d_in[4];  // [512,4096]
    const float* w_vb  = (const float*)d_in[5];  // [512,4096]
    const float* w_o   = (const float*)d_in[6];  // [4096,4096]

    float* attn_out = (float*)d_out;                                   // [2,2048,4096]
    float* ckv      = (float*)d_out + (size_t)TOKENS * HID;            // [2,2048,512]

    float *qc, *q, *k, *v, *ao;
    cudaGetSymbolAddress((void**)&qc, g_qc);
    cudaGetSymbolAddress((void**)&q,  g_q);
    cudaGetSymbolAddress((void**)&k,  g_k);
    cudaGetSymbolAddress((void**)&v,  g_v);
    cudaGetSymbolAddress((void**)&ao, g_ao);

    cudaFuncSetAttribute(flash_kernel,
                         cudaFuncAttributeMaxDynamicSharedMemorySize,
                         FLASH_SMEM_BYTES);

    cudaStream_t stream = 0;  // harness captures the default-stream work

    // projections
    run_sgemm(X,   w_qa,  qc,  TOKENS, QRANK,  HID,    stream);  // q_c
    run_sgemm(qc,  w_qb,  q,   TOKENS, MODEL,  QRANK,  stream);  // q
    run_sgemm(X,   w_kva, ckv, TOKENS, KVRANK, HID,    stream);  // compressed_kv (output #2)
    run_sgemm(ckv, w_kb,  k,   TOKENS, MODEL,  KVRANK, stream);  // k
    run_sgemm(ckv, w_vb,  v,   TOKENS, MODEL,  KVRANK, stream);  // v

    // causal attention
    dim3 fgrid(SEQ / FTM, NHEADS, BATCH);
    flash_kernel<<<fgrid, 256, FLASH_SMEM_BYTES, stream>>>(q, k, v, ao);

    // output projection
    run_sgemm(ao, w_o, attn_out, TOKENS, HID, MODEL, stream);
}

// round 3
// speedup vs baseline: 1.7721x; 1.7721x over previous
#include <cuda_runtime.h>
#include <cuda_bf16.h>
#include <cstdint>
#include <cstddef>

// ---------------------------------------------------------------------------
// Problem constants
// ---------------------------------------------------------------------------
static constexpr int BATCH   = 2;
static constexpr int SEQ     = 2048;
static constexpr int HID     = 4096;
static constexpr int NHEADS  = 32;
static constexpr int HDIM    = 128;
static constexpr int QRANK   = 1536;
static constexpr int KVRANK  = 512;
static constexpr int TOKENS  = BATCH * SEQ;            // 4096
static constexpr int MODEL   = NHEADS * HDIM;          // 4096
static constexpr float SM_SCALE = 0.08838834764831845f; // 1/sqrt(128)

// ---------------------------------------------------------------------------
// Scratch (static device allocations; no cudaMalloc anywhere)
// ---------------------------------------------------------------------------
__device__ float g_qc[(size_t)TOKENS * QRANK];
__device__ float g_q [(size_t)TOKENS * MODEL];
__device__ float g_k [(size_t)TOKENS * MODEL];
__device__ float g_v [(size_t)TOKENS * MODEL];
__device__ float g_ao[(size_t)TOKENS * MODEL];

// ---------------------------------------------------------------------------
// Helpers
// ---------------------------------------------------------------------------
__device__ __forceinline__ uint32_t f2tf32(float x) {
    uint32_t r;
    asm("cvt.rna.tf32.f32 %0, %1;" : "=r"(r) : "f"(x));
    return r;
}

__device__ __forceinline__ void mma_tf32(float c[4], const uint32_t a[4],
                                         const uint32_t b[2]) {
    asm volatile(
        "mma.sync.aligned.m16n8k8.row.col.f32.tf32.tf32.f32 "
        "{%0,%1,%2,%3}, {%4,%5,%6,%7}, {%8,%9}, {%0,%1,%2,%3};"
        : "+f"(c[0]), "+f"(c[1]), "+f"(c[2]), "+f"(c[3])
        : "r"(a[0]), "r"(a[1]), "r"(a[2]), "r"(a[3]), "r"(b[0]), "r"(b[1]));
}

// ---------------------------------------------------------------------------
// mma.sync tf32 GEMM:  C[M,N] = A[M,K] @ B[K,N]   (both row-major)
// CTA tile 128x128, BK=32, 256 threads (8 warps, 2x4), warp tile 64x32.
// Double-buffered smem; A stride 36 floats, B stride 136 floats
// (bank-conflict-free fragment loads; float4-aligned stores).
// ---------------------------------------------------------------------------
static constexpr int A_LD = 36;                    // floats
static constexpr int B_LD = 136;                   // floats
static constexpr int A_FLOATS = 128 * A_LD;        // 4608
static constexpr int B_FLOATS = 32 * B_LD;         // 4352
static constexpr int STAGE_FLOATS = A_FLOATS + B_FLOATS;   // 8960
static constexpr int GEMM_SMEM_BYTES = 2 * STAGE_FLOATS * 4; // 71680

__global__ __launch_bounds__(256) void gemm_mma(
    const float* __restrict__ A, const float* __restrict__ B,
    float* __restrict__ C, int M, int N, int K)
{
    extern __shared__ uint32_t smu[];
    const int tid  = threadIdx.x;
    const int wid  = tid >> 5;
    const int lane = tid & 31;
    const int warpM = wid >> 2;     // 0..1
    const int warpN = wid & 3;      // 0..3
    const int m0 = blockIdx.y * 128;
    const int n0 = blockIdx.x * 128;
    const int r  = lane >> 2;       // 0..7
    const int cq = lane & 3;        // 0..3

    float acc[4][4][4];
#pragma unroll
    for (int mi = 0; mi < 4; mi++)
#pragma unroll
        for (int nj = 0; nj < 4; nj++)
#pragma unroll
            for (int t = 0; t < 4; t++) acc[mi][nj][t] = 0.f;

    // producer mappings
    const int ar  = tid >> 3;               // A row 0..127 (+ i*32? no: slot math below)
    const int ac4 = (tid & 7) << 2;         // A col {0,4,...,28}
    const int bslot_r = tid >> 5;           // base B row, +8 per i? see loop
    const int bn4 = (tid & 31) << 2;        // B col {0..124}

    float4 av[4], bv[4];
    const int KT = K >> 5;

    // prologue: load chunk 0
    {
        const int k0 = 0;
#pragma unroll
        for (int i = 0; i < 4; i++) {
            int rr = ar + 0;  (void)rr;
            av[i] = *(const float4*)(A + (size_t)(m0 + (tid >> 3) + i * 32) * K + k0 + ac4);
            bv[i] = *(const float4*)(B + (size_t)(k0 + (tid >> 5) + i * 8) * N + n0 + bn4);
        }
    }
    // store chunk 0 into stage 0
    {
        uint32_t* as = smu;
        uint32_t* bs = smu + A_FLOATS;
#pragma unroll
        for (int i = 0; i < 4; i++) {
            uint4 t = { f2tf32(av[i].x), f2tf32(av[i].y), f2tf32(av[i].z), f2tf32(av[i].w) };
            *(uint4*)&as[((tid >> 3) + i * 32) * A_LD + ac4] = t;
            uint4 u = { f2tf32(bv[i].x), f2tf32(bv[i].y), f2tf32(bv[i].z), f2tf32(bv[i].w) };
            *(uint4*)&bs[((tid >> 5) + i * 8) * B_LD + bn4] = u;
        }
    }
    __syncthreads();

    for (int it = 0; it < KT; ++it) {
        const int s = it & 1;
        // prefetch next chunk to registers
        if (it + 1 < KT) {
            const int k0 = (it + 1) << 5;
#pragma unroll
            for (int i = 0; i < 4; i++) {
                av[i] = *(const float4*)(A + (size_t)(m0 + (tid >> 3) + i * 32) * K + k0 + ac4);
                bv[i] = *(const float4*)(B + (size_t)(k0 + (tid >> 5) + i * 8) * N + n0 + bn4);
            }
        }

        // compute on stage s
        const uint32_t* as = smu + s * STAGE_FLOATS;
        const uint32_t* bs = smu + s * STAGE_FLOATS + A_FLOATS;
#pragma unroll
        for (int ks = 0; ks < 4; ++ks) {
            uint32_t af[4][4];
#pragma unroll
            for (int mi = 0; mi < 4; mi++) {
                int rb = (warpM * 64 + mi * 16 + r) * A_LD + ks * 8 + cq;
                af[mi][0] = as[rb];
                af[mi][1] = as[rb + 8 * A_LD];
                af[mi][2] = as[rb + 4];
                af[mi][3] = as[rb + 8 * A_LD + 4];
            }
            uint32_t bf[4][2];
#pragma unroll
            for (int nj = 0; nj < 4; nj++) {
                int bb = (ks * 8 + cq) * B_LD + warpN * 32 + nj * 8 + r;
                bf[nj][0] = bs[bb];
                bf[nj][1] = bs[bb + 4 * B_LD];
            }
#pragma unroll
            for (int mi = 0; mi < 4; mi++)
#pragma unroll
                for (int nj = 0; nj < 4; nj++)
                    mma_tf32(acc[mi][nj], af[mi], bf[nj]);
        }

        // store next chunk into the other stage
        if (it + 1 < KT) {
            uint32_t* asn = smu + (s ^ 1) * STAGE_FLOATS;
            uint32_t* bsn = smu + (s ^ 1) * STAGE_FLOATS + A_FLOATS;
#pragma unroll
            for (int i = 0; i < 4; i++) {
                uint4 t = { f2tf32(av[i].x), f2tf32(av[i].y), f2tf32(av[i].z), f2tf32(av[i].w) };
                *(uint4*)&asn[((tid >> 3) + i * 32) * A_LD + ac4] = t;
                uint4 u = { f2tf32(bv[i].x), f2tf32(bv[i].y), f2tf32(bv[i].z), f2tf32(bv[i].w) };
                *(uint4*)&bsn[((tid >> 5) + i * 8) * B_LD + bn4] = u;
            }
            __syncthreads();
        }
    }

    // epilogue
#pragma unroll
    for (int mi = 0; mi < 4; mi++) {
        const int row0 = m0 + warpM * 64 + mi * 16 + r;
#pragma unroll
        for (int nj = 0; nj < 4; nj++) {
            const int col = n0 + warpN * 32 + nj * 8 + 2 * cq;
            *(float2*)&C[(size_t)row0 * N + col] =
                make_float2(acc[mi][nj][0], acc[mi][nj][1]);
            *(float2*)&C[(size_t)(row0 + 8) * N + col] =
                make_float2(acc[mi][nj][2], acc[mi][nj][3]);
        }
    }
}

// ---------------------------------------------------------------------------
// Flash attention (causal), fp32 — verified round-1 version, unchanged.
// ---------------------------------------------------------------------------
static constexpr int FTM = 64;
static constexpr int FTN = 64;
static constexpr int QS_LD = HDIM + 4;
static constexpr int PS_LD = FTN + 4;
static constexpr int FLASH_SMEM_FLOATS =
    3 * FTM * QS_LD + FTM * PS_LD + 3 * FTM;
static constexpr int FLASH_SMEM_BYTES = FLASH_SMEM_FLOATS * 4;

__global__ __launch_bounds__(256) void flash_kernel(
    const float* __restrict__ Q, const float* __restrict__ K,
    const float* __restrict__ V, float* __restrict__ O)
{
    extern __shared__ float fsh[];
    float* Qs   = fsh;
    float* Ks   = Qs + FTM * QS_LD;
    float* Vs   = Ks + FTM * QS_LD;
    float* Ps   = Vs + FTM * QS_LD;
    float* rmax = Ps + FTM * PS_LD;
    float* rsum = rmax + FTM;
    float* corr = rsum + FTM;

    const int tid   = threadIdx.x;
    const int mtile = blockIdx.x;
    const int head  = blockIdx.y;
    const int b     = blockIdx.z;
    const int m0    = mtile * FTM;
    const size_t base = ((size_t)b * SEQ) * MODEL + (size_t)head * HDIM;

    for (int it = tid; it < FTM * (HDIM / 4); it += 256) {
        int r  = it >> 5;
        int c4 = (it & 31) << 2;
        *(float4*)&Qs[r * QS_LD + c4] =
            *(const float4*)&Q[base + (size_t)(m0 + r) * MODEL + c4];
    }
    if (tid < FTM) { rmax[tid] = -1e30f; rsum[tid] = 0.f; }

    const int sm = tid >> 4;
    const int sn = tid & 15;

    float o[4][8];
#pragma unroll
    for (int i = 0; i < 4; i++)
#pragma unroll
        for (int j = 0; j < 8; j++) o[i][j] = 0.f;

    const int ntiles = mtile + 1;
    for (int t = 0; t < ntiles; t++) {
        const int n0 = t * FTN;
        __syncthreads();
        for (int it = tid; it < FTN * (HDIM / 4); it += 256) {
            int r  = it >> 5;
            int c4 = (it & 31) << 2;
            size_t g = base + (size_t)(n0 + r) * MODEL + c4;
            *(float4*)&Ks[r * QS_LD + c4] = *(const float4*)&K[g];
            *(float4*)&Vs[r * QS_LD + c4] = *(const float4*)&V[g];
        }
        __syncthreads();

        float s[4][4];
#pragma unroll
        for (int i = 0; i < 4; i++)
#pragma unroll
            for (int j = 0; j < 4; j++) s[i][j] = 0.f;

#pragma unroll 4
        for (int d4 = 0; d4 < HDIM / 4; d4++) {
            float4 qa[4], kb[4];
#pragma unroll
            for (int i = 0; i < 4; i++)
                qa[i] = *(const float4*)&Qs[(sm * 4 + i) * QS_LD + d4 * 4];
#pragma unroll
            for (int j = 0; j < 4; j++)
                kb[j] = *(const float4*)&Ks[(sn * 4 + j) * QS_LD + d4 * 4];
#pragma unroll
            for (int i = 0; i < 4; i++)
#pragma unroll
                for (int j = 0; j < 4; j++) {
                    s[i][j] = fmaf(qa[i].x, kb[j].x, s[i][j]);
                    s[i][j] = fmaf(qa[i].y, kb[j].y, s[i][j]);
                    s[i][j] = fmaf(qa[i].z, kb[j].z, s[i][j]);
                    s[i][j] = fmaf(qa[i].w, kb[j].w, s[i][j]);
                }
        }

#pragma unroll
        for (int i = 0; i < 4; i++) {
            int mq = m0 + sm * 4 + i;
#pragma unroll
            for (int j = 0; j < 4; j++) {
                int kn = n0 + sn * 4 + j;
                s[i][j] = (kn <= mq) ? s[i][j] * SM_SCALE : -1e30f;
            }
        }

#pragma unroll
        for (int i = 0; i < 4; i++) {
            const int row = sm * 4 + i;
            float tmax = fmaxf(fmaxf(s[i][0], s[i][1]), fmaxf(s[i][2], s[i][3]));
#pragma unroll
            for (int off = 1; off < 16; off <<= 1)
                tmax = fmaxf(tmax, __shfl_xor_sync(0xffffffffu, tmax, off));
            float oldmax = rmax[row];
            float nmax = fmaxf(oldmax, tmax);
            float p0 = __expf(s[i][0] - nmax);
            float p1 = __expf(s[i][1] - nmax);
            float p2 = __expf(s[i][2] - nmax);
            float p3 = __expf(s[i][3] - nmax);
            float tsum = p0 + p1 + p2 + p3;
#pragma unroll
            for (int off = 1; off < 16; off <<= 1)
                tsum += __shfl_xor_sync(0xffffffffu, tsum, off);
            float c = __expf(oldmax - nmax);
            if (sn == 0) {
                rmax[row] = nmax;
                rsum[row] = rsum[row] * c + tsum;
                corr[row] = c;
            }
            *(float4*)&Ps[row * PS_LD + sn * 4] = make_float4(p0, p1, p2, p3);
        }
        __syncthreads();

#pragma unroll
        for (int i = 0; i < 4; i++) {
            float c = corr[sm * 4 + i];
#pragma unroll
            for (int j = 0; j < 8; j++) o[i][j] *= c;
        }
#pragma unroll 4
        for (int kk = 0; kk < FTN; kk++) {
            float4 v0 = *(const float4*)&Vs[kk * QS_LD + sn * 8];
            float4 v1 = *(const float4*)&Vs[kk * QS_LD + sn * 8 + 4];
#pragma unroll
            for (int i = 0; i < 4; i++) {
                float p = Ps[(sm * 4 + i) * PS_LD + kk];
                o[i][0] = fmaf(p, v0.x, o[i][0]);
                o[i][1] = fmaf(p, v0.y, o[i][1]);
                o[i][2] = fmaf(p, v0.z, o[i][2]);
                o[i][3] = fmaf(p, v0.w, o[i][3]);
                o[i][4] = fmaf(p, v1.x, o[i][4]);
                o[i][5] = fmaf(p, v1.y, o[i][5]);
                o[i][6] = fmaf(p, v1.z, o[i][6]);
                o[i][7] = fmaf(p, v1.w, o[i][7]);
            }
        }
    }
    __syncthreads();

#pragma unroll
    for (int i = 0; i < 4; i++) {
        int row = sm * 4 + i;
        float inv = 1.f / rsum[row];
        float4 w0 = make_float4(o[i][0] * inv, o[i][1] * inv, o[i][2] * inv, o[i][3] * inv);
        float4 w1 = make_float4(o[i][4] * inv, o[i][5] * inv, o[i][6] * inv, o[i][7] * inv);
        size_t g = base + (size_t)(m0 + row) * MODEL + sn * 8;
        *(float4*)&O[g]     = w0;
        *(float4*)&O[g + 4] = w1;
    }
}

// ---------------------------------------------------------------------------
// Launch
// ---------------------------------------------------------------------------
static inline void run_gemm(const float* A, const float* B, float* C,
                            int M, int N, int K, cudaStream_t stream)
{
    dim3 grid(N / 128, M / 128);
    gemm_mma<<<grid, 256, GEMM_SMEM_BYTES, stream>>>(A, B, C, M, N, K);
}

extern "C" void kernel_launch(void* const* d_in, const int* in_sizes, int n_in,
                              void* d_out, int out_size)
{
    (void)in_sizes; (void)n_in; (void)out_size;
    const float* X     = (const float*)d_in[0];  // [4096,4096]
    const float* w_qa  = (const float*)d_in[1];  // [4096,1536]
    const float* w_qb  = (const float*)d_in[2];  // [1536,4096]
    const float* w_kva = (const float*)d_in[3];  // [4096,512]
    const float* w_kb  = (const float*)d_in[4];  // [512,4096]
    const float* w_vb  = (const float*)d_in[5];  // [512,4096]
    const float* w_o   = (const float*)d_in[6];  // [4096,4096]

    float* attn_out = (float*)d_out;
    float* ckv      = (float*)d_out + (size_t)TOKENS * HID;

    float *qc, *q, *k, *v, *ao;
    cudaGetSymbolAddress((void**)&qc, g_qc);
    cudaGetSymbolAddress((void**)&q,  g_q);
    cudaGetSymbolAddress((void**)&k,  g_k);
    cudaGetSymbolAddress((void**)&v,  g_v);
    cudaGetSymbolAddress((void**)&ao, g_ao);

    cudaFuncSetAttribute(flash_kernel,
                         cudaFuncAttributeMaxDynamicSharedMemorySize,
                         FLASH_SMEM_BYTES);
    cudaFuncSetAttribute(gemm_mma,
                         cudaFuncAttributeMaxDynamicSharedMemorySize,
                         GEMM_SMEM_BYTES);

    cudaStream_t stream = 0;

    // projections (tensor-core tf32, weights consumed in native [K,N] layout)
    run_gemm(X,   w_qa,  qc,  TOKENS, QRANK,  HID,    stream);
    run_gemm(qc,  w_qb,  q,   TOKENS, MODEL,  QRANK,  stream);
    run_gemm(X,   w_kva, ckv, TOKENS, KVRANK, HID,    stream);
    run_gemm(ckv, w_kb,  k,   TOKENS, MODEL,  KVRANK, stream);
    run_gemm(ckv, w_vb,  v,   TOKENS, MODEL,  KVRANK, stream);

    // causal attention (fp32, next optimization target)
    dim3 fgrid(SEQ / FTM, NHEADS, BATCH);
    flash_kernel<<<fgrid, 256, FLASH_SMEM_BYTES, stream>>>(q, k, v, ao);

    // output projection
    run_gemm(ao, w_o, attn_out, TOKENS, HID, MODEL, stream);
}

// round 4
// speedup vs baseline: 3.5064x; 1.9786x over previous
#include <cuda_runtime.h>
#include <cuda_bf16.h>
#include <cstdint>
#include <cstddef>

// ---------------------------------------------------------------------------
// Problem constants
// ---------------------------------------------------------------------------
static constexpr int BATCH   = 2;
static constexpr int SEQ     = 2048;
static constexpr int HID     = 4096;
static constexpr int NHEADS  = 32;
static constexpr int HDIM    = 128;
static constexpr int QRANK   = 1536;
static constexpr int KVRANK  = 512;
static constexpr int TOKENS  = BATCH * SEQ;            // 4096
static constexpr int MODEL   = NHEADS * HDIM;          // 4096
static constexpr float SM_SCALE = 0.08838834764831845f; // 1/sqrt(128)

// ---------------------------------------------------------------------------
// Scratch (static device allocations; no cudaMalloc anywhere)
// ---------------------------------------------------------------------------
__device__ float g_qc[(size_t)TOKENS * QRANK];
__device__ float g_q [(size_t)TOKENS * MODEL];
__device__ float g_k [(size_t)TOKENS * MODEL];
__device__ float g_v [(size_t)TOKENS * MODEL];
__device__ float g_ao[(size_t)TOKENS * MODEL];

// ---------------------------------------------------------------------------
// Helpers
// ---------------------------------------------------------------------------
__device__ __forceinline__ uint32_t f2tf32(float x) {
    uint32_t r;
    asm("cvt.rna.tf32.f32 %0, %1;" : "=r"(r) : "f"(x));
    return r;
}

__device__ __forceinline__ void mma_tf32(float c[4], const uint32_t a[4],
                                         const uint32_t b[2]) {
    asm volatile(
        "mma.sync.aligned.m16n8k8.row.col.f32.tf32.tf32.f32 "
        "{%0,%1,%2,%3}, {%4,%5,%6,%7}, {%8,%9}, {%0,%1,%2,%3};"
        : "+f"(c[0]), "+f"(c[1]), "+f"(c[2]), "+f"(c[3])
        : "r"(a[0]), "r"(a[1]), "r"(a[2]), "r"(a[3]), "r"(b[0]), "r"(b[1]));
}

// ---------------------------------------------------------------------------
// mma.sync tf32 GEMM:  C[M,N] = A[M,K] @ B[K,N]  (both row-major)
// (verified round-3 version, unchanged)
// ---------------------------------------------------------------------------
static constexpr int A_LD = 36;
static constexpr int B_LD = 136;
static constexpr int A_FLOATS = 128 * A_LD;
static constexpr int B_FLOATS = 32 * B_LD;
static constexpr int STAGE_FLOATS = A_FLOATS + B_FLOATS;
static constexpr int GEMM_SMEM_BYTES = 2 * STAGE_FLOATS * 4;

__global__ __launch_bounds__(256) void gemm_mma(
    const float* __restrict__ A, const float* __restrict__ B,
    float* __restrict__ C, int M, int N, int K)
{
    extern __shared__ uint32_t smu[];
    const int tid  = threadIdx.x;
    const int wid  = tid >> 5;
    const int lane = tid & 31;
    const int warpM = wid >> 2;
    const int warpN = wid & 3;
    const int m0 = blockIdx.y * 128;
    const int n0 = blockIdx.x * 128;
    const int r  = lane >> 2;
    const int cq = lane & 3;

    float acc[4][4][4];
#pragma unroll
    for (int mi = 0; mi < 4; mi++)
#pragma unroll
        for (int nj = 0; nj < 4; nj++)
#pragma unroll
            for (int t = 0; t < 4; t++) acc[mi][nj][t] = 0.f;

    const int ac4 = (tid & 7) << 2;
    const int bn4 = (tid & 31) << 2;

    float4 av[4], bv[4];
    const int KT = K >> 5;

    {
        const int k0 = 0;
#pragma unroll
        for (int i = 0; i < 4; i++) {
            av[i] = *(const float4*)(A + (size_t)(m0 + (tid >> 3) + i * 32) * K + k0 + ac4);
            bv[i] = *(const float4*)(B + (size_t)(k0 + (tid >> 5) + i * 8) * N + n0 + bn4);
        }
    }
    {
        uint32_t* as = smu;
        uint32_t* bs = smu + A_FLOATS;
#pragma unroll
        for (int i = 0; i < 4; i++) {
            uint4 t = { f2tf32(av[i].x), f2tf32(av[i].y), f2tf32(av[i].z), f2tf32(av[i].w) };
            *(uint4*)&as[((tid >> 3) + i * 32) * A_LD + ac4] = t;
            uint4 u = { f2tf32(bv[i].x), f2tf32(bv[i].y), f2tf32(bv[i].z), f2tf32(bv[i].w) };
            *(uint4*)&bs[((tid >> 5) + i * 8) * B_LD + bn4] = u;
        }
    }
    __syncthreads();

    for (int it = 0; it < KT; ++it) {
        const int s = it & 1;
        if (it + 1 < KT) {
            const int k0 = (it + 1) << 5;
#pragma unroll
            for (int i = 0; i < 4; i++) {
                av[i] = *(const float4*)(A + (size_t)(m0 + (tid >> 3) + i * 32) * K + k0 + ac4);
                bv[i] = *(const float4*)(B + (size_t)(k0 + (tid >> 5) + i * 8) * N + n0 + bn4);
            }
        }

        const uint32_t* as = smu + s * STAGE_FLOATS;
        const uint32_t* bs = smu + s * STAGE_FLOATS + A_FLOATS;
#pragma unroll
        for (int ks = 0; ks < 4; ++ks) {
            uint32_t af[4][4];
#pragma unroll
            for (int mi = 0; mi < 4; mi++) {
                int rb = (warpM * 64 + mi * 16 + r) * A_LD + ks * 8 + cq;
                af[mi][0] = as[rb];
                af[mi][1] = as[rb + 8 * A_LD];
                af[mi][2] = as[rb + 4];
                af[mi][3] = as[rb + 8 * A_LD + 4];
            }
            uint32_t bf[4][2];
#pragma unroll
            for (int nj = 0; nj < 4; nj++) {
                int bb = (ks * 8 + cq) * B_LD + warpN * 32 + nj * 8 + r;
                bf[nj][0] = bs[bb];
                bf[nj][1] = bs[bb + 4 * B_LD];
            }
#pragma unroll
            for (int mi = 0; mi < 4; mi++)
#pragma unroll
                for (int nj = 0; nj < 4; nj++)
                    mma_tf32(acc[mi][nj], af[mi], bf[nj]);
        }

        if (it + 1 < KT) {
            uint32_t* asn = smu + (s ^ 1) * STAGE_FLOATS;
            uint32_t* bsn = smu + (s ^ 1) * STAGE_FLOATS + A_FLOATS;
#pragma unroll
            for (int i = 0; i < 4; i++) {
                uint4 t = { f2tf32(av[i].x), f2tf32(av[i].y), f2tf32(av[i].z), f2tf32(av[i].w) };
                *(uint4*)&asn[((tid >> 3) + i * 32) * A_LD + ac4] = t;
                uint4 u = { f2tf32(bv[i].x), f2tf32(bv[i].y), f2tf32(bv[i].z), f2tf32(bv[i].w) };
                *(uint4*)&bsn[((tid >> 5) + i * 8) * B_LD + bn4] = u;
            }
            __syncthreads();
        }
    }

#pragma unroll
    for (int mi = 0; mi < 4; mi++) {
        const int row0 = m0 + warpM * 64 + mi * 16 + r;
#pragma unroll
        for (int nj = 0; nj < 4; nj++) {
            const int col = n0 + warpN * 32 + nj * 8 + 2 * cq;
            *(float2*)&C[(size_t)row0 * N + col] =
                make_float2(acc[mi][nj][0], acc[mi][nj][1]);
            *(float2*)&C[(size_t)(row0 + 8) * N + col] =
                make_float2(acc[mi][nj][2], acc[mi][nj][3]);
        }
    }
}

// ---------------------------------------------------------------------------
// Tensor-core flash attention (causal), tf32 mma + fp32 online softmax.
// CTA: 128 queries, iterates 64-key tiles. 8 warps; warp w owns q rows
// [w*16, w*16+16) -> softmax fully warp-local.
// Smem: K(64x132) | V(64x132) (also used to stage Q once), P(128x68).
// Grid: (SEQ/128, NHEADS, BATCH), 256 threads.
// ---------------------------------------------------------------------------
static constexpr int FQ = 128;
static constexpr int FK = 64;
static constexpr int KV_LD = 132;      // uint32 units; 132 % 32 = 4 (conflict-free frags)
static constexpr int P_LD  = 68;       // 68 % 32 = 4
static constexpr int FLASH_SMEM_BYTES = (128 * KV_LD + 128 * P_LD) * 4;  // 102,400

__global__ __launch_bounds__(256) void flash_tc(
    const float* __restrict__ Q, const float* __restrict__ K,
    const float* __restrict__ V, float* __restrict__ O)
{
    extern __shared__ uint32_t fsm[];
    uint32_t* kvs = fsm;               // K rows 0..63, V rows 64..127
    uint32_t* Ps  = fsm + 128 * KV_LD;

    const int tid  = threadIdx.x;
    const int wq   = tid >> 5;         // warp id: q rows wq*16..wq*16+15
    const int lane = tid & 31;
    const int r    = lane >> 2;        // 0..7
    const int cq   = lane & 3;         // 0..3
    const int mtile = blockIdx.x;
    const int head  = blockIdx.y;
    const int b     = blockIdx.z;
    const int m0    = mtile * FQ;
    const size_t base = ((size_t)b * SEQ) * MODEL + (size_t)head * HDIM;

    // ---- stage Q (pre-scaled, tf32) through smem, load q-fragments ----
    for (int it = tid; it < 128 * 32; it += 256) {
        int row = it >> 5, c4 = (it & 31) << 2;
        float4 v = *(const float4*)&Q[base + (size_t)(m0 + row) * MODEL + c4];
        uint4 t = { f2tf32(v.x * SM_SCALE), f2tf32(v.y * SM_SCALE),
                    f2tf32(v.z * SM_SCALE), f2tf32(v.w * SM_SCALE) };
        *(uint4*)&kvs[row * KV_LD + c4] = t;
    }
    __syncthreads();

    uint32_t qf[16][4];
#pragma unroll
    for (int ks = 0; ks < 16; ks++) {
        int rb = (wq * 16 + r) * KV_LD + ks * 8 + cq;
        qf[ks][0] = kvs[rb];
        qf[ks][1] = kvs[rb + 8 * KV_LD];
        qf[ks][2] = kvs[rb + 4];
        qf[ks][3] = kvs[rb + 8 * KV_LD + 4];
    }

    float of[16][4];
#pragma unroll
    for (int nj = 0; nj < 16; nj++)
#pragma unroll
        for (int t = 0; t < 4; t++) of[nj][t] = 0.f;

    float mrow0 = -1e30f, mrow1 = -1e30f, lrow0 = 0.f, lrow1 = 0.f;
    const int row0 = m0 + wq * 16 + r;
    const int row1 = row0 + 8;

    const int NT = 2 * (mtile + 1);
    for (int t = 0; t < NT; t++) {
        const int n0 = t * FK;
        __syncthreads();   // prior iteration's smem reads complete
        for (int it = tid; it < 64 * 32; it += 256) {
            int row = it >> 5, c4 = (it & 31) << 2;
            size_t g = base + (size_t)(n0 + row) * MODEL + c4;
            float4 k4 = *(const float4*)&K[g];
            float4 v4 = *(const float4*)&V[g];
            uint4 tk = { f2tf32(k4.x), f2tf32(k4.y), f2tf32(k4.z), f2tf32(k4.w) };
            uint4 tv = { f2tf32(v4.x), f2tf32(v4.y), f2tf32(v4.z), f2tf32(v4.w) };
            *(uint4*)&kvs[row * KV_LD + c4]        = tk;
            *(uint4*)&kvs[(64 + row) * KV_LD + c4] = tv;
        }
        __syncthreads();

        // ---- S = Q K^T (scaled): 8 n-blocks of 8 keys ----
        float sc[8][4];
#pragma unroll
        for (int nj = 0; nj < 8; nj++)
#pragma unroll
            for (int e = 0; e < 4; e++) sc[nj][e] = 0.f;

#pragma unroll
        for (int ks = 0; ks < 16; ks++) {
#pragma unroll
            for (int nj = 0; nj < 8; nj++) {
                uint32_t bb[2];
                int ib = (nj * 8 + r) * KV_LD + ks * 8 + cq;
                bb[0] = kvs[ib];
                bb[1] = kvs[ib + 4];
                mma_tf32(sc[nj], qf[ks], bb);
            }
        }

        // ---- causal mask (only tiles touching the diagonal) ----
        if (n0 + FK - 1 > m0) {
#pragma unroll
            for (int nj = 0; nj < 8; nj++) {
                int kk = n0 + nj * 8 + 2 * cq;
                if (kk     > row0) sc[nj][0] = -1e30f;
                if (kk + 1 > row0) sc[nj][1] = -1e30f;
                if (kk     > row1) sc[nj][2] = -1e30f;
                if (kk + 1 > row1) sc[nj][3] = -1e30f;
            }
        }

        // ---- online softmax (rows warp-local; quad shuffles) ----
        float tmax0 = -1e30f, tmax1 = -1e30f;
#pragma unroll
        for (int nj = 0; nj < 8; nj++) {
            tmax0 = fmaxf(tmax0, fmaxf(sc[nj][0], sc[nj][1]));
            tmax1 = fmaxf(tmax1, fmaxf(sc[nj][2], sc[nj][3]));
        }
        tmax0 = fmaxf(tmax0, __shfl_xor_sync(0xffffffffu, tmax0, 1));
        tmax0 = fmaxf(tmax0, __shfl_xor_sync(0xffffffffu, tmax0, 2));
        tmax1 = fmaxf(tmax1, __shfl_xor_sync(0xffffffffu, tmax1, 1));
        tmax1 = fmaxf(tmax1, __shfl_xor_sync(0xffffffffu, tmax1, 2));

        float nm0 = fmaxf(mrow0, tmax0);
        float nm1 = fmaxf(mrow1, tmax1);
        float c0 = __expf(mrow0 - nm0);
        float c1 = __expf(mrow1 - nm1);
        float ts0 = 0.f, ts1 = 0.f;
#pragma unroll
        for (int nj = 0; nj < 8; nj++) {
            float p0 = __expf(sc[nj][0] - nm0);
            float p1 = __expf(sc[nj][1] - nm0);
            float p2 = __expf(sc[nj][2] - nm1);
            float p3 = __expf(sc[nj][3] - nm1);
            ts0 += p0 + p1;
            ts1 += p2 + p3;
            uint2 u0 = { f2tf32(p0), f2tf32(p1) };
            uint2 u1 = { f2tf32(p2), f2tf32(p3) };
            *(uint2*)&Ps[(wq * 16 + r) * P_LD + nj * 8 + 2 * cq]       = u0;
            *(uint2*)&Ps[(wq * 16 + r + 8) * P_LD + nj * 8 + 2 * cq]   = u1;
        }
        ts0 += __shfl_xor_sync(0xffffffffu, ts0, 1);
        ts0 += __shfl_xor_sync(0xffffffffu, ts0, 2);
        ts1 += __shfl_xor_sync(0xffffffffu, ts1, 1);
        ts1 += __shfl_xor_sync(0xffffffffu, ts1, 2);

        mrow0 = nm0; mrow1 = nm1;
        lrow0 = lrow0 * c0 + ts0;
        lrow1 = lrow1 * c1 + ts1;
#pragma unroll
        for (int nj = 0; nj < 16; nj++) {
            of[nj][0] *= c0; of[nj][1] *= c0;
            of[nj][2] *= c1; of[nj][3] *= c1;
        }
        __syncwarp();   // P visible to other lanes of this warp

        // ---- O += P V : contraction over 64 keys (8 k8-steps) ----
#pragma unroll
        for (int ks = 0; ks < 8; ks++) {
            uint32_t ap[4];
            int rb = (wq * 16 + r) * P_LD + ks * 8 + cq;
            ap[0] = Ps[rb];
            ap[1] = Ps[rb + 8 * P_LD];
            ap[2] = Ps[rb + 4];
            ap[3] = Ps[rb + 8 * P_LD + 4];
#pragma unroll
            for (int nj = 0; nj < 16; nj++) {
                uint32_t bb[2];
                int ib = (64 + ks * 8 + cq) * KV_LD + nj * 8 + r;
                bb[0] = kvs[ib];
                bb[1] = kvs[ib + 4 * KV_LD];
                mma_tf32(of[nj], ap, bb);
            }
        }
    }

    // ---- epilogue: divide by l, write O ----
    const float inv0 = 1.f / lrow0;
    const float inv1 = 1.f / lrow1;
#pragma unroll
    for (int nj = 0; nj < 16; nj++) {
        int col = nj * 8 + 2 * cq;
        *(float2*)&O[base + (size_t)row0 * MODEL + col] =
            make_float2(of[nj][0] * inv0, of[nj][1] * inv0);
        *(float2*)&O[base + (size_t)row1 * MODEL + col] =
            make_float2(of[nj][2] * inv1, of[nj][3] * inv1);
    }
}

// ---------------------------------------------------------------------------
// Launch
// ---------------------------------------------------------------------------
static inline void run_gemm(const float* A, const float* B, float* C,
                            int M, int N, int K, cudaStream_t stream)
{
    dim3 grid(N / 128, M / 128);
    gemm_mma<<<grid, 256, GEMM_SMEM_BYTES, stream>>>(A, B, C, M, N, K);
}

extern "C" void kernel_launch(void* const* d_in, const int* in_sizes, int n_in,
                              void* d_out, int out_size)
{
    (void)in_sizes; (void)n_in; (void)out_size;
    const float* X     = (const float*)d_in[0];
    const float* w_qa  = (const float*)d_in[1];
    const float* w_qb  = (const float*)d_in[2];
    const float* w_kva = (const float*)d_in[3];
    const float* w_kb  = (const float*)d_in[4];
    const float* w_vb  = (const float*)d_in[5];
    const float* w_o   = (const float*)d_in[6];

    float* attn_out = (float*)d_out;
    float* ckv      = (float*)d_out + (size_t)TOKENS * HID;

    float *qc, *q, *k, *v, *ao;
    cudaGetSymbolAddress((void**)&qc, g_qc);
    cudaGetSymbolAddress((void**)&q,  g_q);
    cudaGetSymbolAddress((void**)&k,  g_k);
    cudaGetSymbolAddress((void**)&v,  g_v);
    cudaGetSymbolAddress((void**)&ao, g_ao);

    cudaFuncSetAttribute(gemm_mma,
                         cudaFuncAttributeMaxDynamicSharedMemorySize,
                         GEMM_SMEM_BYTES);
    cudaFuncSetAttribute(flash_tc,
                         cudaFuncAttributeMaxDynamicSharedMemorySize,
                         FLASH_SMEM_BYTES);

    cudaStream_t stream = 0;

    // projections (tensor-core tf32)
    run_gemm(X,   w_qa,  qc,  TOKENS, QRANK,  HID,    stream);
    run_gemm(qc,  w_qb,  q,   TOKENS, MODEL,  QRANK,  stream);
    run_gemm(X,   w_kva, ckv, TOKENS, KVRANK, HID,    stream);
    run_gemm(ckv, w_kb,  k,   TOKENS, MODEL,  KVRANK, stream);
    run_gemm(ckv, w_vb,  v,   TOKENS, MODEL,  KVRANK, stream);

    // causal attention (tensor-core tf32)
    dim3 fgrid(SEQ / FQ, NHEADS, BATCH);
    flash_tc<<<fgrid, 256, FLASH_SMEM_BYTES, stream>>>(q, k, v, ao);

    // output projection
    run_gemm(ao, w_o, attn_out, TOKENS, HID, MODEL, stream);
}

// round 5
// speedup vs baseline: 3.5292x; 1.0065x over previous
#include <cuda_runtime.h>
#include <cuda_bf16.h>
#include <cstdint>
#include <cstddef>

// ---------------------------------------------------------------------------
// Problem constants
// ---------------------------------------------------------------------------
static constexpr int BATCH   = 2;
static constexpr int SEQ     = 2048;
static constexpr int HID     = 4096;
static constexpr int NHEADS  = 32;
static constexpr int HDIM    = 128;
static constexpr int QRANK   = 1536;
static constexpr int KVRANK  = 512;
static constexpr int TOKENS  = BATCH * SEQ;            // 4096
static constexpr int MODEL   = NHEADS * HDIM;          // 4096
static constexpr float SM_SCALE = 0.08838834764831845f; // 1/sqrt(128)

// ---------------------------------------------------------------------------
// Scratch (static device allocations; no cudaMalloc anywhere)
// ---------------------------------------------------------------------------
__device__ float g_qc[(size_t)TOKENS * QRANK];
__device__ float g_q [(size_t)TOKENS * MODEL];
__device__ float g_k [(size_t)TOKENS * MODEL];
__device__ float g_v [(size_t)TOKENS * MODEL];
__device__ float g_ao[(size_t)TOKENS * MODEL];

// ---------------------------------------------------------------------------
// Helpers
// ---------------------------------------------------------------------------
__device__ __forceinline__ uint32_t f2tf32(float x) {
    uint32_t r;
    asm("cvt.rna.tf32.f32 %0, %1;" : "=r"(r) : "f"(x));
    return r;
}

__device__ __forceinline__ void mma_tf32(float c[4], const uint32_t a[4],
                                         const uint32_t b[2]) {
    asm volatile(
        "mma.sync.aligned.m16n8k8.row.col.f32.tf32.tf32.f32 "
        "{%0,%1,%2,%3}, {%4,%5,%6,%7}, {%8,%9}, {%0,%1,%2,%3};"
        : "+f"(c[0]), "+f"(c[1]), "+f"(c[2]), "+f"(c[3])
        : "r"(a[0]), "r"(a[1]), "r"(a[2]), "r"(a[3]), "r"(b[0]), "r"(b[1]));
}

// ---------------------------------------------------------------------------
// mma.sync tf32 GEMM:  C[M,N] = A[M,K] @ B[K,N]  (both row-major)
// (verified round-3 version, unchanged)
// ---------------------------------------------------------------------------
static constexpr int A_LD = 36;
static constexpr int B_LD = 136;
static constexpr int A_FLOATS = 128 * A_LD;
static constexpr int B_FLOATS = 32 * B_LD;
static constexpr int STAGE_FLOATS = A_FLOATS + B_FLOATS;
static constexpr int GEMM_SMEM_BYTES = 2 * STAGE_FLOATS * 4;

__global__ __launch_bounds__(256) void gemm_mma(
    const float* __restrict__ A, const float* __restrict__ B,
    float* __restrict__ C, int M, int N, int K)
{
    extern __shared__ uint32_t smu[];
    const int tid  = threadIdx.x;
    const int wid  = tid >> 5;
    const int lane = tid & 31;
    const int warpM = wid >> 2;
    const int warpN = wid & 3;
    const int m0 = blockIdx.y * 128;
    const int n0 = blockIdx.x * 128;
    const int r  = lane >> 2;
    const int cq = lane & 3;

    float acc[4][4][4];
#pragma unroll
    for (int mi = 0; mi < 4; mi++)
#pragma unroll
        for (int nj = 0; nj < 4; nj++)
#pragma unroll
            for (int t = 0; t < 4; t++) acc[mi][nj][t] = 0.f;

    const int ac4 = (tid & 7) << 2;
    const int bn4 = (tid & 31) << 2;

    float4 av[4], bv[4];
    const int KT = K >> 5;

    {
        const int k0 = 0;
#pragma unroll
        for (int i = 0; i < 4; i++) {
            av[i] = *(const float4*)(A + (size_t)(m0 + (tid >> 3) + i * 32) * K + k0 + ac4);
            bv[i] = *(const float4*)(B + (size_t)(k0 + (tid >> 5) + i * 8) * N + n0 + bn4);
        }
    }
    {
        uint32_t* as = smu;
        uint32_t* bs = smu + A_FLOATS;
#pragma unroll
        for (int i = 0; i < 4; i++) {
            uint4 t = { f2tf32(av[i].x), f2tf32(av[i].y), f2tf32(av[i].z), f2tf32(av[i].w) };
            *(uint4*)&as[((tid >> 3) + i * 32) * A_LD + ac4] = t;
            uint4 u = { f2tf32(bv[i].x), f2tf32(bv[i].y), f2tf32(bv[i].z), f2tf32(bv[i].w) };
            *(uint4*)&bs[((tid >> 5) + i * 8) * B_LD + bn4] = u;
        }
    }
    __syncthreads();

    for (int it = 0; it < KT; ++it) {
        const int s = it & 1;
        if (it + 1 < KT) {
            const int k0 = (it + 1) << 5;
#pragma unroll
            for (int i = 0; i < 4; i++) {
                av[i] = *(const float4*)(A + (size_t)(m0 + (tid >> 3) + i * 32) * K + k0 + ac4);
                bv[i] = *(const float4*)(B + (size_t)(k0 + (tid >> 5) + i * 8) * N + n0 + bn4);
            }
        }

        const uint32_t* as = smu + s * STAGE_FLOATS;
        const uint32_t* bs = smu + s * STAGE_FLOATS + A_FLOATS;
#pragma unroll
        for (int ks = 0; ks < 4; ++ks) {
            uint32_t af[4][4];
#pragma unroll
            for (int mi = 0; mi < 4; mi++) {
                int rb = (warpM * 64 + mi * 16 + r) * A_LD + ks * 8 + cq;
                af[mi][0] = as[rb];
                af[mi][1] = as[rb + 8 * A_LD];
                af[mi][2] = as[rb + 4];
                af[mi][3] = as[rb + 8 * A_LD + 4];
            }
            uint32_t bf[4][2];
#pragma unroll
            for (int nj = 0; nj < 4; nj++) {
                int bb = (ks * 8 + cq) * B_LD + warpN * 32 + nj * 8 + r;
                bf[nj][0] = bs[bb];
                bf[nj][1] = bs[bb + 4 * B_LD];
            }
#pragma unroll
            for (int mi = 0; mi < 4; mi++)
#pragma unroll
                for (int nj = 0; nj < 4; nj++)
                    mma_tf32(acc[mi][nj], af[mi], bf[nj]);
        }

        if (it + 1 < KT) {
            uint32_t* asn = smu + (s ^ 1) * STAGE_FLOATS;
            uint32_t* bsn = smu + (s ^ 1) * STAGE_FLOATS + A_FLOATS;
#pragma unroll
            for (int i = 0; i < 4; i++) {
                uint4 t = { f2tf32(av[i].x), f2tf32(av[i].y), f2tf32(av[i].z), f2tf32(av[i].w) };
                *(uint4*)&asn[((tid >> 3) + i * 32) * A_LD + ac4] = t;
                uint4 u = { f2tf32(bv[i].x), f2tf32(bv[i].y), f2tf32(bv[i].z), f2tf32(bv[i].w) };
                *(uint4*)&bsn[((tid >> 5) + i * 8) * B_LD + bn4] = u;
            }
            __syncthreads();
        }
    }

#pragma unroll
    for (int mi = 0; mi < 4; mi++) {
        const int row0 = m0 + warpM * 64 + mi * 16 + r;
#pragma unroll
        for (int nj = 0; nj < 4; nj++) {
            const int col = n0 + warpN * 32 + nj * 8 + 2 * cq;
            *(float2*)&C[(size_t)row0 * N + col] =
                make_float2(acc[mi][nj][0], acc[mi][nj][1]);
            *(float2*)&C[(size_t)(row0 + 8) * N + col] =
                make_float2(acc[mi][nj][2], acc[mi][nj][3]);
        }
    }
}

// ---------------------------------------------------------------------------
// Tensor-core flash attention (causal), tf32 mma + fp32 online softmax.
// v3: double-buffered KV smem with register prefetch (gemm pattern) — hides
// global-load latency behind QK (K prefetch) and PV (V prefetch); one
// __syncthreads per key-tile.
// CTA: 128 queries; 8 warps, warp w owns q rows [w*16, w*16+16).
// ---------------------------------------------------------------------------
static constexpr int FQ = 128;
static constexpr int FK = 64;
static constexpr int KV_LD = 132;                 // u32; %32==4 -> conflict-free frags
static constexpr int P_LD  = 68;                  // u32; %32==4
static constexpr int KVBUF = 128 * KV_LD;         // one stage: K rows 0-63, V rows 64-127
static constexpr int FLASH_SMEM_BYTES = (2 * KVBUF + 128 * P_LD) * 4;  // 169,984

__global__ __launch_bounds__(256) void flash_tc(
    const float* __restrict__ Q, const float* __restrict__ K,
    const float* __restrict__ V, float* __restrict__ O)
{
    extern __shared__ uint32_t fsm[];
    uint32_t* Ps = fsm + 2 * KVBUF;

    const int tid  = threadIdx.x;
    const int wq   = tid >> 5;
    const int lane = tid & 31;
    const int r    = lane >> 2;
    const int cq   = lane & 3;
    const int mtile = blockIdx.x;
    const int head  = blockIdx.y;
    const int b     = blockIdx.z;
    const int m0    = mtile * FQ;
    const size_t base = ((size_t)b * SEQ) * MODEL + (size_t)head * HDIM;

    const int strow = tid >> 5;            // staging row within 32-row slab? (see loops)
    (void)strow;

    // ---- stage Q (pre-scaled tf32) through kv buffer 0, read q-fragments ----
    for (int it = tid; it < 128 * 32; it += 256) {
        int row = it >> 5, c4 = (it & 31) << 2;
        float4 v = *(const float4*)&Q[base + (size_t)(m0 + row) * MODEL + c4];
        uint4 t = { f2tf32(v.x * SM_SCALE), f2tf32(v.y * SM_SCALE),
                    f2tf32(v.z * SM_SCALE), f2tf32(v.w * SM_SCALE) };
        *(uint4*)&fsm[row * KV_LD + c4] = t;
    }
    __syncthreads();

    uint32_t qf[16][4];
#pragma unroll
    for (int ks = 0; ks < 16; ks++) {
        int rb = (wq * 16 + r) * KV_LD + ks * 8 + cq;
        qf[ks][0] = fsm[rb];
        qf[ks][1] = fsm[rb + 8 * KV_LD];
        qf[ks][2] = fsm[rb + 4];
        qf[ks][3] = fsm[rb + 8 * KV_LD + 4];
    }
    __syncthreads();   // all warps done reading Q before tile-0 overwrites buf0

    // ---- prologue: tile 0 KV into buffer 0 ----
    for (int it = tid; it < 64 * 32; it += 256) {
        int row = it >> 5, c4 = (it & 31) << 2;
        size_t g = base + (size_t)row * MODEL + c4;
        float4 k4 = *(const float4*)&K[g];
        float4 v4 = *(const float4*)&V[g];
        uint4 tk = { f2tf32(k4.x), f2tf32(k4.y), f2tf32(k4.z), f2tf32(k4.w) };
        uint4 tv = { f2tf32(v4.x), f2tf32(v4.y), f2tf32(v4.z), f2tf32(v4.w) };
        *(uint4*)&fsm[row * KV_LD + c4]        = tk;
        *(uint4*)&fsm[(64 + row) * KV_LD + c4] = tv;
    }
    __syncthreads();

    float of[16][4];
#pragma unroll
    for (int nj = 0; nj < 16; nj++)
#pragma unroll
        for (int t = 0; t < 4; t++) of[nj][t] = 0.f;

    float mrow0 = -1e30f, mrow1 = -1e30f, lrow0 = 0.f, lrow1 = 0.f;
    const int row0 = m0 + wq * 16 + r;
    const int row1 = row0 + 8;

    const int prow = tid >> 5;    // prefetch row base helper (slot>>5 pattern)
    (void)prow;

    const int NT = 2 * (mtile + 1);
    for (int t = 0; t < NT; t++) {
        const uint32_t* kb = fsm + (t & 1) * KVBUF;
        uint32_t*       nb = fsm + ((t + 1) & 1) * KVBUF;
        const bool hasnext = (t + 1 < NT);
        const int n0 = t * FK;
        const int n1 = n0 + FK;

        // ---- prefetch K(t+1) to registers (covered by QK phase) ----
        uint4 pk[8];
        if (hasnext) {
#pragma unroll
            for (int i = 0; i < 8; i++) {
                int slot = tid + i * 256;
                int row = slot >> 5, c4 = (slot & 31) << 2;
                float4 k4 = *(const float4*)&K[base + (size_t)(n1 + row) * MODEL + c4];
                pk[i] = make_uint4(f2tf32(k4.x), f2tf32(k4.y), f2tf32(k4.z), f2tf32(k4.w));
            }
        }

        // ---- S = Q K^T : 8 n-blocks of 8 keys ----
        float sc[8][4];
#pragma unroll
        for (int nj = 0; nj < 8; nj++)
#pragma unroll
            for (int e = 0; e < 4; e++) sc[nj][e] = 0.f;

#pragma unroll
        for (int ks = 0; ks < 16; ks++) {
#pragma unroll
            for (int nj = 0; nj < 8; nj++) {
                uint32_t bb[2];
                int ib = (nj * 8 + r) * KV_LD + ks * 8 + cq;
                bb[0] = kb[ib];
                bb[1] = kb[ib + 4];
                mma_tf32(sc[nj], qf[ks], bb);
            }
        }

        // ---- causal mask (diagonal tiles only) ----
        if (n0 + FK - 1 > m0) {
#pragma unroll
            for (int nj = 0; nj < 8; nj++) {
                int kk = n0 + nj * 8 + 2 * cq;
                if (kk     > row0) sc[nj][0] = -1e30f;
                if (kk + 1 > row0) sc[nj][1] = -1e30f;
                if (kk     > row1) sc[nj][2] = -1e30f;
                if (kk + 1 > row1) sc[nj][3] = -1e30f;
            }
        }

        // ---- online softmax (warp-local rows; quad shuffles) ----
        float tmax0 = -1e30f, tmax1 = -1e30f;
#pragma unroll
        for (int nj = 0; nj < 8; nj++) {
            tmax0 = fmaxf(tmax0, fmaxf(sc[nj][0], sc[nj][1]));
            tmax1 = fmaxf(tmax1, fmaxf(sc[nj][2], sc[nj][3]));
        }
        tmax0 = fmaxf(tmax0, __shfl_xor_sync(0xffffffffu, tmax0, 1));
        tmax0 = fmaxf(tmax0, __shfl_xor_sync(0xffffffffu, tmax0, 2));
        tmax1 = fmaxf(tmax1, __shfl_xor_sync(0xffffffffu, tmax1, 1));
        tmax1 = fmaxf(tmax1, __shfl_xor_sync(0xffffffffu, tmax1, 2));

        float nm0 = fmaxf(mrow0, tmax0);
        float nm1 = fmaxf(mrow1, tmax1);
        float c0 = __expf(mrow0 - nm0);
        float c1 = __expf(mrow1 - nm1);
        float ts0 = 0.f, ts1 = 0.f;
#pragma unroll
        for (int nj = 0; nj < 8; nj++) {
            float p0 = __expf(sc[nj][0] - nm0);
            float p1 = __expf(sc[nj][1] - nm0);
            float p2 = __expf(sc[nj][2] - nm1);
            float p3 = __expf(sc[nj][3] - nm1);
            ts0 += p0 + p1;
            ts1 += p2 + p3;
            uint2 u0 = { f2tf32(p0), f2tf32(p1) };
            uint2 u1 = { f2tf32(p2), f2tf32(p3) };
            *(uint2*)&Ps[(wq * 16 + r) * P_LD + nj * 8 + 2 * cq]     = u0;
            *(uint2*)&Ps[(wq * 16 + r + 8) * P_LD + nj * 8 + 2 * cq] = u1;
        }
        ts0 += __shfl_xor_sync(0xffffffffu, ts0, 1);
        ts0 += __shfl_xor_sync(0xffffffffu, ts0, 2);
        ts1 += __shfl_xor_sync(0xffffffffu, ts1, 1);
        ts1 += __shfl_xor_sync(0xffffffffu, ts1, 2);

        mrow0 = nm0; mrow1 = nm1;
        lrow0 = lrow0 * c0 + ts0;
        lrow1 = lrow1 * c1 + ts1;
#pragma unroll
        for (int nj = 0; nj < 16; nj++) {
            of[nj][0] *= c0; of[nj][1] *= c0;
            of[nj][2] *= c1; of[nj][3] *= c1;
        }
        __syncwarp();   // P visible within warp

        // ---- drain K prefetch into next buffer; start V prefetch ----
        uint4 pv[8];
        if (hasnext) {
#pragma unroll
            for (int i = 0; i < 8; i++) {
                int slot = tid + i * 256;
                int row = slot >> 5, c4 = (slot & 31) << 2;
                *(uint4*)&nb[row * KV_LD + c4] = pk[i];
            }
#pragma unroll
            for (int i = 0; i < 8; i++) {
                int slot = tid + i * 256;
                int row = slot >> 5, c4 = (slot & 31) << 2;
                float4 v4 = *(const float4*)&V[base + (size_t)(n1 + row) * MODEL + c4];
                pv[i] = make_uint4(f2tf32(v4.x), f2tf32(v4.y), f2tf32(v4.z), f2tf32(v4.w));
            }
        }

        // ---- O += P V (covers V prefetch latency) ----
#pragma unroll
        for (int ks = 0; ks < 8; ks++) {
            uint32_t ap[4];
            int rb = (wq * 16 + r) * P_LD + ks * 8 + cq;
            ap[0] = Ps[rb];
            ap[1] = Ps[rb + 8 * P_LD];
            ap[2] = Ps[rb + 4];
            ap[3] = Ps[rb + 8 * P_LD + 4];
#pragma unroll
            for (int nj = 0; nj < 16; nj++) {
                uint32_t bb[2];
                int ib = (64 + ks * 8 + cq) * KV_LD + nj * 8 + r;
                bb[0] = kb[ib];
                bb[1] = kb[ib + 4 * KV_LD];
                mma_tf32(of[nj], ap, bb);
            }
        }

        // ---- drain V prefetch; single barrier per iteration ----
        if (hasnext) {
#pragma unroll
            for (int i = 0; i < 8; i++) {
                int slot = tid + i * 256;
                int row = slot >> 5, c4 = (slot & 31) << 2;
                *(uint4*)&nb[(64 + row) * KV_LD + c4] = pv[i];
            }
        }
        __syncthreads();
    }

    // ---- epilogue ----
    const float inv0 = 1.f / lrow0;
    const float inv1 = 1.f / lrow1;
#pragma unroll
    for (int nj = 0; nj < 16; nj++) {
        int col = nj * 8 + 2 * cq;
        *(float2*)&O[base + (size_t)row0 * MODEL + col] =
            make_float2(of[nj][0] * inv0, of[nj][1] * inv0);
        *(float2*)&O[base + (size_t)row1 * MODEL + col] =
            make_float2(of[nj][2] * inv1, of[nj][3] * inv1);
    }
}

// ---------------------------------------------------------------------------
// Launch
// ---------------------------------------------------------------------------
static inline void run_gemm(const float* A, const float* B, float* C,
                            int M, int N, int K, cudaStream_t stream)
{
    dim3 grid(N / 128, M / 128);
    gemm_mma<<<grid, 256, GEMM_SMEM_BYTES, stream>>>(A, B, C, M, N, K);
}

extern "C" void kernel_launch(void* const* d_in, const int* in_sizes, int n_in,
                              void* d_out, int out_size)
{
    (void)in_sizes; (void)n_in; (void)out_size;
    const float* X     = (const float*)d_in[0];
    const float* w_qa  = (const float*)d_in[1];
    const float* w_qb  = (const float*)d_in[2];
    const float* w_kva = (const float*)d_in[3];
    const float* w_kb  = (const float*)d_in[4];
    const float* w_vb  = (const float*)d_in[5];
    const float* w_o   = (const float*)d_in[6];

    float* attn_out = (float*)d_out;
    float* ckv      = (float*)d_out + (size_t)TOKENS * HID;

    float *qc, *q, *k, *v, *ao;
    cudaGetSymbolAddress((void**)&qc, g_qc);
    cudaGetSymbolAddress((void**)&q,  g_q);
    cudaGetSymbolAddress((void**)&k,  g_k);
    cudaGetSymbolAddress((void**)&v,  g_v);
    cudaGetSymbolAddress((void**)&ao, g_ao);

    cudaFuncSetAttribute(gemm_mma,
                         cudaFuncAttributeMaxDynamicSharedMemorySize,
                         GEMM_SMEM_BYTES);
    cudaFuncSetAttribute(flash_tc,
                         cudaFuncAttributeMaxDynamicSharedMemorySize,
                         FLASH_SMEM_BYTES);

    cudaStream_t stream = 0;

    // projections (tensor-core tf32)
    run_gemm(X,   w_qa,  qc,  TOKENS, QRANK,  HID,    stream);
    run_gemm(qc,  w_qb,  q,   TOKENS, MODEL,  QRANK,  stream);
    run_gemm(X,   w_kva, ckv, TOKENS, KVRANK, HID,    stream);
    run_gemm(ckv, w_kb,  k,   TOKENS, MODEL,  KVRANK, stream);
    run_gemm(ckv, w_vb,  v,   TOKENS, MODEL,  KVRANK, stream);

    // causal attention (tensor-core tf32, double-buffered)
    dim3 fgrid(SEQ / FQ, NHEADS, BATCH);
    flash_tc<<<fgrid, 256, FLASH_SMEM_BYTES, stream>>>(q, k, v, ao);

    // output projection
    run_gemm(ao, w_o, attn_out, TOKENS, HID, MODEL, stream);
}